// round 1
// baseline (speedup 1.0000x reference)
#include <cuda_runtime.h>

#define N_NODES 100000
#define DIM 64

// Scratch: ping-pong h buffers + aggregation buffer (float4 for 16B alignment).
__device__ float4 g_hbuf[2][(size_t)N_NODES * 16];
__device__ float4 g_hn[(size_t)N_NODES * 16];

__global__ void zero_kernel(float4* __restrict__ p, int n4) {
    int i = blockIdx.x * blockDim.x + threadIdx.x;
    if (i < n4) p[i] = make_float4(0.f, 0.f, 0.f, 0.f);
}

// out[:, 0:64] = x   (out row stride = 256 floats = 64 float4)
__global__ void copy_x_kernel(const float4* __restrict__ x, float4* __restrict__ out, int n16) {
    int i = blockIdx.x * blockDim.x + threadIdx.x;
    if (i >= n16) return;
    int v = i >> 4, c = i & 15;
    out[(size_t)v * 64 + c] = x[i];
}

// h_n[dst[e]] += a[e] * h[src[e]]   -- 16 threads per edge, float4 each.
__global__ void aggregate_kernel(const float4* __restrict__ hin,
                                 const int* __restrict__ src,
                                 const int* __restrict__ dst,
                                 const float* __restrict__ a,
                                 float* __restrict__ hn, int ne) {
    long long gid = (long long)blockIdx.x * blockDim.x + threadIdx.x;
    int e = (int)(gid >> 4);
    if (e >= ne) return;
    int c = (int)(gid & 15);
    int s = __ldg(src + e);
    int d = __ldg(dst + e);
    float w = __ldg(a + e);
    float4 v = __ldg(hin + ((size_t)s << 4) + c);
    float* p = hn + ((size_t)d << 6) + (c << 2);
    atomicAdd(p + 0, v.x * w);
    atomicAdd(p + 1, v.y * w);
    atomicAdd(p + 2, v.z * w);
    atomicAdd(p + 3, v.w * w);
}

// h_out = lrelu((h+hn)@W1 + b1) + lrelu((h*hn)@W2 + b2); also written into out concat slot.
// Tile: 64 nodes x 64 dims per block, 256 threads, 4x4 register micro-tile per thread,
// two GEMM paths (S@W1, P@W2) accumulated simultaneously.
__global__ void mlp_kernel(const float4* __restrict__ hin,
                           const float4* __restrict__ hn,
                           const float4* __restrict__ W1,
                           const float*  __restrict__ b1,
                           const float4* __restrict__ W2,
                           const float*  __restrict__ b2,
                           float4* __restrict__ hout,
                           float*  __restrict__ out,
                           int out_off, int n) {
    extern __shared__ float sm[];
    float* Ssh  = sm;                // [64][68]  (pad 4 to break bank conflicts)
    float* Psh  = Ssh + 64 * 68;     // [64][68]
    float* W1sh = Psh + 64 * 68;     // [64][64] row-major [k][j]
    float* W2sh = W1sh + 4096;       // [64][64]
    float* b1sh = W2sh + 4096;       // [64]
    float* b2sh = b1sh + 64;         // [64]

    int tid = threadIdx.x;
    int node0 = blockIdx.x << 6;

    // Stage weights (flat copy: 1024 float4 each)
    for (int i = tid; i < 1024; i += 256) {
        ((float4*)W1sh)[i] = __ldg(W1 + i);
        ((float4*)W2sh)[i] = __ldg(W2 + i);
    }
    if (tid < 64) { b1sh[tid] = __ldg(b1 + tid); b2sh[tid] = __ldg(b2 + tid); }

    // Stage node tile: compute S = h + hn, P = h * hn
    for (int i = tid; i < 1024; i += 256) {
        int nl = i >> 4, c = i & 15;
        int v = node0 + nl;
        float4 hv = make_float4(0.f, 0.f, 0.f, 0.f);
        float4 nv = make_float4(0.f, 0.f, 0.f, 0.f);
        if (v < n) {
            hv = __ldg(hin + ((size_t)v << 4) + c);
            nv = __ldg(hn  + ((size_t)v << 4) + c);
        }
        float4 s4 = make_float4(hv.x + nv.x, hv.y + nv.y, hv.z + nv.z, hv.w + nv.w);
        float4 p4 = make_float4(hv.x * nv.x, hv.y * nv.y, hv.z * nv.z, hv.w * nv.w);
        *(float4*)(Ssh + nl * 68 + (c << 2)) = s4;
        *(float4*)(Psh + nl * 68 + (c << 2)) = p4;
    }
    __syncthreads();

    int tx = tid & 15, ty = tid >> 4;     // tx: dim group (4 dims), ty: node group (4 nodes)
    float acc1[4][4] = {};
    float acc2[4][4] = {};

#pragma unroll 8
    for (int k = 0; k < 64; k++) {
        float4 w1 = *(const float4*)(W1sh + (k << 6) + (tx << 2));
        float4 w2 = *(const float4*)(W2sh + (k << 6) + (tx << 2));
#pragma unroll
        for (int i = 0; i < 4; i++) {
            float s = Ssh[(ty * 4 + i) * 68 + k];
            float p = Psh[(ty * 4 + i) * 68 + k];
            acc1[i][0] += s * w1.x; acc1[i][1] += s * w1.y;
            acc1[i][2] += s * w1.z; acc1[i][3] += s * w1.w;
            acc2[i][0] += p * w2.x; acc2[i][1] += p * w2.y;
            acc2[i][2] += p * w2.z; acc2[i][3] += p * w2.w;
        }
    }

    int j0 = tx << 2;
#pragma unroll
    for (int i = 0; i < 4; i++) {
        int v = node0 + ty * 4 + i;
        if (v >= n) continue;
        float4 o;
        {
            float e1 = acc1[i][0] + b1sh[j0 + 0]; e1 = e1 > 0.f ? e1 : 0.01f * e1;
            float e2 = acc2[i][0] + b2sh[j0 + 0]; e2 = e2 > 0.f ? e2 : 0.01f * e2;
            o.x = e1 + e2;
        }
        {
            float e1 = acc1[i][1] + b1sh[j0 + 1]; e1 = e1 > 0.f ? e1 : 0.01f * e1;
            float e2 = acc2[i][1] + b2sh[j0 + 1]; e2 = e2 > 0.f ? e2 : 0.01f * e2;
            o.y = e1 + e2;
        }
        {
            float e1 = acc1[i][2] + b1sh[j0 + 2]; e1 = e1 > 0.f ? e1 : 0.01f * e1;
            float e2 = acc2[i][2] + b2sh[j0 + 2]; e2 = e2 > 0.f ? e2 : 0.01f * e2;
            o.z = e1 + e2;
        }
        {
            float e1 = acc1[i][3] + b1sh[j0 + 3]; e1 = e1 > 0.f ? e1 : 0.01f * e1;
            float e2 = acc2[i][3] + b2sh[j0 + 3]; e2 = e2 > 0.f ? e2 : 0.01f * e2;
            o.w = e1 + e2;
        }
        hout[((size_t)v << 4) + tx] = o;
        *(float4*)(out + (size_t)v * 256 + out_off + j0) = o;
    }
}

extern "C" void kernel_launch(void* const* d_in, const int* in_sizes, int n_in,
                              void* d_out, int out_size) {
    const float* x   = (const float*)d_in[0];
    const float* a   = (const float*)d_in[1];
    const float* W1s = (const float*)d_in[2];
    const float* b1s = (const float*)d_in[3];
    const float* W2s = (const float*)d_in[4];
    const float* b2s = (const float*)d_in[5];
    const int*   src = (const int*)d_in[6];
    const int*   dst = (const int*)d_in[7];
    float* out = (float*)d_out;

    int n   = in_sizes[0] / DIM;
    int ne  = in_sizes[6];
    int n16 = n * 16;

    void* p;
    cudaGetSymbolAddress(&p, g_hbuf);
    float4* hbuf = (float4*)p;
    cudaGetSymbolAddress(&p, g_hn);
    float4* hn = (float4*)p;

    const int SMEM = (64 * 68 * 2 + 4096 * 2 + 128) * 4;  // 68096 B
    cudaFuncSetAttribute(mlp_kernel, cudaFuncAttributeMaxDynamicSharedMemorySize, SMEM);

    copy_x_kernel<<<(n16 + 255) / 256, 256>>>((const float4*)x, (float4*)out, n16);

    const float4* hin = (const float4*)x;
    for (int l = 0; l < 3; l++) {
        float4* hout = hbuf + (size_t)(l & 1) * ((size_t)N_NODES * 16);

        zero_kernel<<<(n16 + 255) / 256, 256>>>(hn, n16);

        int agg_blocks = (int)(((long long)ne * 16 + 255) >> 8);
        aggregate_kernel<<<agg_blocks, 256>>>(hin, src, dst, a, (float*)hn, ne);

        mlp_kernel<<<(n + 63) / 64, 256, SMEM>>>(
            hin, hn,
            (const float4*)(W1s + (size_t)l * 4096), b1s + l * 64,
            (const float4*)(W2s + (size_t)l * 4096), b2s + l * 64,
            hout, out, DIM * (l + 1), n);

        hin = hout;
    }
}

// round 2
// speedup vs baseline: 2.3373x; 2.3373x over previous
#include <cuda_runtime.h>

#define N_NODES 100000
#define N_EDGES 3200000
#define DIM 64

// Scratch (device globals: no allocation allowed in kernel_launch).
__device__ float4 g_hbuf[2][(size_t)N_NODES * 16];
__device__ float4 g_hn[(size_t)N_NODES * 16];
__device__ int    g_off[N_NODES + 1];
__device__ int    g_cur[N_NODES];
__device__ int    g_srcp[N_EDGES];
__device__ float  g_ap[N_EDGES];

// ---------------- CSR build ----------------

__global__ void zero_int_kernel(int* __restrict__ p, int n) {
    int i = blockIdx.x * blockDim.x + threadIdx.x;
    if (i < n) p[i] = 0;
}

__global__ void hist_kernel(const int* __restrict__ dst, int* __restrict__ cnt, int ne) {
    int e = blockIdx.x * blockDim.x + threadIdx.x;
    if (e < ne) atomicAdd(&cnt[__ldg(dst + e)], 1);
}

// Single-block exclusive scan over cnt[0..n) -> off[0..n]; also cur[v] = off[v].
__global__ void scan_kernel(int* __restrict__ cnt, int* __restrict__ off,
                            int* __restrict__ cur, int n) {
    __shared__ int sh[1024];
    int t = threadIdx.x;
    int C = (n + 1023) >> 10;
    int base = t * C;
    int sum = 0;
    for (int i = 0; i < C; i++) {
        int idx = base + i;
        if (idx < n) sum += cnt[idx];
    }
    sh[t] = sum;
    __syncthreads();
    // Hillis-Steele inclusive scan
    for (int d = 1; d < 1024; d <<= 1) {
        int tmp = (t >= d) ? sh[t - d] : 0;
        __syncthreads();
        sh[t] += tmp;
        __syncthreads();
    }
    int run = sh[t] - sum;  // exclusive base for this chunk
    for (int i = 0; i < C; i++) {
        int idx = base + i;
        if (idx < n) {
            int c = cnt[idx];
            off[idx] = run;
            cur[idx] = run;
            run += c;
        }
    }
    if (t == 1023) off[n] = sh[1023];
}

__global__ void scatter_kernel(const int* __restrict__ src, const int* __restrict__ dst,
                               const float* __restrict__ a,
                               int* __restrict__ cur,
                               int* __restrict__ srcp, float* __restrict__ ap, int ne) {
    int e = blockIdx.x * blockDim.x + threadIdx.x;
    if (e >= ne) return;
    int d = __ldg(dst + e);
    int pos = atomicAdd(&cur[d], 1);
    srcp[pos] = __ldg(src + e);
    ap[pos]   = __ldg(a + e);
}

// ---------------- Per-layer kernels ----------------

// out[:, 0:64] = x   (out row stride = 256 floats = 64 float4)
__global__ void copy_x_kernel(const float4* __restrict__ x, float4* __restrict__ out, int n16) {
    int i = blockIdx.x * blockDim.x + threadIdx.x;
    if (i >= n16) return;
    int v = i >> 4, c = i & 15;
    out[(size_t)v * 64 + c] = x[i];
}

// CSR gather-accumulate: h_n[v] = sum over edges of a_e * h[src_e].
// 16 threads per node, one float4 segment each. No atomics, single store.
__global__ void aggregate_csr(const float4* __restrict__ hin,
                              const int* __restrict__ off,
                              const int* __restrict__ srcp,
                              const float* __restrict__ ap,
                              float4* __restrict__ hn, int n) {
    int g = blockIdx.x * blockDim.x + threadIdx.x;
    int v = g >> 4;
    if (v >= n) return;
    int c = g & 15;
    int i = __ldg(off + v), end = __ldg(off + v + 1);
    float4 acc = make_float4(0.f, 0.f, 0.f, 0.f);
    if (i < end) {
        int s = __ldg(srcp + i);
        float w = __ldg(ap + i);
        for (; i + 1 < end; i++) {
            int s2 = __ldg(srcp + i + 1);
            float w2 = __ldg(ap + i + 1);
            float4 hv = __ldg(hin + ((size_t)s << 4) + c);
            acc.x += w * hv.x; acc.y += w * hv.y;
            acc.z += w * hv.z; acc.w += w * hv.w;
            s = s2; w = w2;
        }
        float4 hv = __ldg(hin + ((size_t)s << 4) + c);
        acc.x += w * hv.x; acc.y += w * hv.y;
        acc.z += w * hv.z; acc.w += w * hv.w;
    }
    hn[((size_t)v << 4) + c] = acc;
}

// h_out = lrelu((h+hn)@W1 + b1) + lrelu((h*hn)@W2 + b2); also written to out concat slot.
__global__ void mlp_kernel(const float4* __restrict__ hin,
                           const float4* __restrict__ hn,
                           const float4* __restrict__ W1,
                           const float*  __restrict__ b1,
                           const float4* __restrict__ W2,
                           const float*  __restrict__ b2,
                           float4* __restrict__ hout,
                           float*  __restrict__ out,
                           int out_off, int n) {
    extern __shared__ float sm[];
    float* Ssh  = sm;                // [64][68]
    float* Psh  = Ssh + 64 * 68;     // [64][68]
    float* W1sh = Psh + 64 * 68;     // [64][64] [k][j]
    float* W2sh = W1sh + 4096;
    float* b1sh = W2sh + 4096;
    float* b2sh = b1sh + 64;

    int tid = threadIdx.x;
    int node0 = blockIdx.x << 6;

    for (int i = tid; i < 1024; i += 256) {
        ((float4*)W1sh)[i] = __ldg(W1 + i);
        ((float4*)W2sh)[i] = __ldg(W2 + i);
    }
    if (tid < 64) { b1sh[tid] = __ldg(b1 + tid); b2sh[tid] = __ldg(b2 + tid); }

    for (int i = tid; i < 1024; i += 256) {
        int nl = i >> 4, c = i & 15;
        int v = node0 + nl;
        float4 hv = make_float4(0.f, 0.f, 0.f, 0.f);
        float4 nv = make_float4(0.f, 0.f, 0.f, 0.f);
        if (v < n) {
            hv = __ldg(hin + ((size_t)v << 4) + c);
            nv = __ldg(hn  + ((size_t)v << 4) + c);
        }
        float4 s4 = make_float4(hv.x + nv.x, hv.y + nv.y, hv.z + nv.z, hv.w + nv.w);
        float4 p4 = make_float4(hv.x * nv.x, hv.y * nv.y, hv.z * nv.z, hv.w * nv.w);
        *(float4*)(Ssh + nl * 68 + (c << 2)) = s4;
        *(float4*)(Psh + nl * 68 + (c << 2)) = p4;
    }
    __syncthreads();

    int tx = tid & 15, ty = tid >> 4;
    float acc1[4][4] = {};
    float acc2[4][4] = {};

#pragma unroll 8
    for (int k = 0; k < 64; k++) {
        float4 w1 = *(const float4*)(W1sh + (k << 6) + (tx << 2));
        float4 w2 = *(const float4*)(W2sh + (k << 6) + (tx << 2));
#pragma unroll
        for (int i = 0; i < 4; i++) {
            float s = Ssh[(ty * 4 + i) * 68 + k];
            float p = Psh[(ty * 4 + i) * 68 + k];
            acc1[i][0] += s * w1.x; acc1[i][1] += s * w1.y;
            acc1[i][2] += s * w1.z; acc1[i][3] += s * w1.w;
            acc2[i][0] += p * w2.x; acc2[i][1] += p * w2.y;
            acc2[i][2] += p * w2.z; acc2[i][3] += p * w2.w;
        }
    }

    int j0 = tx << 2;
#pragma unroll
    for (int i = 0; i < 4; i++) {
        int v = node0 + ty * 4 + i;
        if (v >= n) continue;
        float4 o;
        float e1, e2;
        e1 = acc1[i][0] + b1sh[j0 + 0]; e1 = e1 > 0.f ? e1 : 0.01f * e1;
        e2 = acc2[i][0] + b2sh[j0 + 0]; e2 = e2 > 0.f ? e2 : 0.01f * e2; o.x = e1 + e2;
        e1 = acc1[i][1] + b1sh[j0 + 1]; e1 = e1 > 0.f ? e1 : 0.01f * e1;
        e2 = acc2[i][1] + b2sh[j0 + 1]; e2 = e2 > 0.f ? e2 : 0.01f * e2; o.y = e1 + e2;
        e1 = acc1[i][2] + b1sh[j0 + 2]; e1 = e1 > 0.f ? e1 : 0.01f * e1;
        e2 = acc2[i][2] + b2sh[j0 + 2]; e2 = e2 > 0.f ? e2 : 0.01f * e2; o.z = e1 + e2;
        e1 = acc1[i][3] + b1sh[j0 + 3]; e1 = e1 > 0.f ? e1 : 0.01f * e1;
        e2 = acc2[i][3] + b2sh[j0 + 3]; e2 = e2 > 0.f ? e2 : 0.01f * e2; o.w = e1 + e2;
        hout[((size_t)v << 4) + tx] = o;
        *(float4*)(out + (size_t)v * 256 + out_off + j0) = o;
    }
}

extern "C" void kernel_launch(void* const* d_in, const int* in_sizes, int n_in,
                              void* d_out, int out_size) {
    const float* x   = (const float*)d_in[0];
    const float* a   = (const float*)d_in[1];
    const float* W1s = (const float*)d_in[2];
    const float* b1s = (const float*)d_in[3];
    const float* W2s = (const float*)d_in[4];
    const float* b2s = (const float*)d_in[5];
    const int*   src = (const int*)d_in[6];
    const int*   dst = (const int*)d_in[7];
    float* out = (float*)d_out;

    int n   = in_sizes[0] / DIM;
    int ne  = in_sizes[6];
    int n16 = n * 16;

    void* p;
    cudaGetSymbolAddress(&p, g_hbuf);  float4* hbuf = (float4*)p;
    cudaGetSymbolAddress(&p, g_hn);    float4* hn   = (float4*)p;
    cudaGetSymbolAddress(&p, g_off);   int*    off  = (int*)p;
    cudaGetSymbolAddress(&p, g_cur);   int*    cur  = (int*)p;
    cudaGetSymbolAddress(&p, g_srcp);  int*    srcp = (int*)p;
    cudaGetSymbolAddress(&p, g_ap);    float*  ap   = (float*)p;

    const int SMEM = (64 * 68 * 2 + 4096 * 2 + 128) * 4;  // 68096 B
    cudaFuncSetAttribute(mlp_kernel, cudaFuncAttributeMaxDynamicSharedMemorySize, SMEM);

    // ---- CSR build (once per launch; reused for all 3 layers) ----
    zero_int_kernel<<<(n + 1023) / 1024, 1024>>>(cur, n);
    hist_kernel<<<(ne + 255) / 256, 256>>>(dst, cur, ne);
    scan_kernel<<<1, 1024>>>(cur, off, cur, n);   // cnt and cur alias deliberately
    scatter_kernel<<<(ne + 255) / 256, 256>>>(src, dst, a, cur, srcp, ap, ne);

    copy_x_kernel<<<(n16 + 255) / 256, 256>>>((const float4*)x, (float4*)out, n16);

    const float4* hin = (const float4*)x;
    for (int l = 0; l < 3; l++) {
        float4* hout = hbuf + (size_t)(l & 1) * ((size_t)N_NODES * 16);

        aggregate_csr<<<(n16 + 255) / 256, 256>>>(hin, off, srcp, ap, hn, n);

        mlp_kernel<<<(n + 63) / 64, 256, SMEM>>>(
            hin, hn,
            (const float4*)(W1s + (size_t)l * 4096), b1s + l * 64,
            (const float4*)(W2s + (size_t)l * 4096), b2s + l * 64,
            hout, out, DIM * (l + 1), n);

        hin = hout;
    }
}